// round 14
// baseline (speedup 1.0000x reference)
#include <cuda_runtime.h>
#include <cstdint>

#define NN        37449   // total nodes
#define L5_START  4681    // leaf level start
#define L5_COUNT  32768
#define L4_START  585
#define L4_COUNT  4096
#define L3_START  73
#define L2_START  9
#define L1_START  1

// sigmoid(w) for all nodes (internal-level dots + head/tail scalars)
__device__ float g_sw[NN];
// 8 shifted copies of the leaf section: copy s stores leaf l at index
// ((8-s)&7)+l. For LB8=s, vector k's 8 leaves start at copy index
// ((8-s)&7)+s+8k (= 8+8k for s>0, 8k for s=0) -> 32B aligned.
__device__ __align__(32) float g_swl8[8][L5_COUNT + 8];

__global__ void setup_kernel(const float* __restrict__ w) {
    int i = blockIdx.x * blockDim.x + threadIdx.x;
    if (i >= NN) return;
    float sv = 1.0f / (1.0f + __expf(-w[i]));
    g_sw[i] = sv;
    int l = i - L5_START;
    if (l >= 0) {
        #pragma unroll
        for (int s = 0; s < 8; ++s)
            g_swl8[s][((8 - s) & 7) + l] = sv;
    }
}

// ---- 256-bit global memory ops (sm_100+) ----
// Input leaf stream: replay-invariant -> keep-in-L2 hint.
__device__ __forceinline__ void ldg256_keep(float* v, const float* p) {
    asm volatile("ld.global.nc.L2::evict_last.v8.f32 {%0,%1,%2,%3,%4,%5,%6,%7}, [%8];"
                 : "=f"(v[0]), "=f"(v[1]), "=f"(v[2]), "=f"(v[3]),
                   "=f"(v[4]), "=f"(v[5]), "=f"(v[6]), "=f"(v[7])
                 : "l"(p));
}
__device__ __forceinline__ void ldg256(float* v, const float* p) {
    asm volatile("ld.global.nc.v8.f32 {%0,%1,%2,%3,%4,%5,%6,%7}, [%8];"
                 : "=f"(v[0]), "=f"(v[1]), "=f"(v[2]), "=f"(v[3]),
                   "=f"(v[4]), "=f"(v[5]), "=f"(v[6]), "=f"(v[7])
                 : "l"(p));
}
__device__ __forceinline__ void stg256(float* p, const float* v) {
    asm volatile("st.global.v8.f32 [%0], {%1,%2,%3,%4,%5,%6,%7,%8};"
                 :: "l"(p), "f"(v[0]), "f"(v[1]), "f"(v[2]), "f"(v[3]),
                    "f"(v[4]), "f"(v[5]), "f"(v[6]), "f"(v[7])
                 : "memory");
}

// Vector k covers leaves [LB8+8k, LB8+8k+8): a -> parent k (first 8-LB8
// products), b -> parent k+1 (last LB8 products). Parent k = a[k] + b[k-1].
template<int LB8>
__device__ __forceinline__ void vec_ab(const float* x, const float* sv,
                                       float& a, float& b)
{
    float p[8];
    #pragma unroll
    for (int i = 0; i < 8; ++i) p[i] = x[i] * sv[i];
    a = 0.f; b = 0.f;
    #pragma unroll
    for (int i = 0; i < 8 - LB8; ++i) a += p[i];
    #pragma unroll
    for (int i = 8 - LB8; i < 8; ++i) b += p[i];
}

template<int LB8>
__device__ __forceinline__ void emit(float a, float b, int k,
                                     float* __restrict__ s_l4,
                                     float* __restrict__ s_edge, int lane)
{
    if (LB8 == 0) {
        s_l4[k] = a;                       // vector k IS parent k
    } else {
        float bprev = __shfl_up_sync(0xffffffffu, b, 1);
        float val = a;
        if (lane > 0) val += bprev;        // lane-0 parents patched in fixup
        s_l4[k] = val;
        if (lane == 31) s_edge[(k >> 5) + 1] = b;  // feeds parent k+1
    }
}

template<int LB8>
__device__ __forceinline__ void stream_phase(
    const float* __restrict__ rin, float* __restrict__ rout,
    float* __restrict__ s_l4, float* __restrict__ s_edge, int tid)
{
    const float* __restrict__ xb  = rin  + L5_START + LB8;   // 32B aligned
    float*       __restrict__ ob  = rout + L5_START + LB8;   // 32B aligned
    const float* __restrict__ swb = &g_swl8[LB8][LB8 ? 8 : 0];
    const int lane = tid & 31;

    const int NFULL = (LB8 == 0) ? 8 : 7;   // full 512-vector iterations
    #pragma unroll 4
    for (int it = 0; it < NFULL; ++it) {
        const int k = it * 512 + tid;
        float x[8], sv[8];
        ldg256_keep(x, xb  + 8 * k);
        ldg256(sv,     swb + 8 * k);
        stg256(ob + 8 * k, x);
        float a, b;
        vec_ab<LB8>(x, sv, a, b);
        emit<LB8>(a, b, k, s_l4, s_edge, lane);
    }

    if (LB8 != 0) {
        // Peeled it==7: vector 4095 is clipped (only 8-LB8 leaves exist).
        const int k = 7 * 512 + tid;
        float a, b;
        if (k != 4095) {
            float x[8], sv[8];
            ldg256_keep(x, xb  + 8 * k);
            ldg256(sv,     swb + 8 * k);
            stg256(ob + 8 * k, x);
            vec_ab<LB8>(x, sv, a, b);
        } else {
            const float* rp = xb  + 8 * 4095;
            float*       wp = ob  + 8 * 4095;
            const float* sp = swb + 8 * 4095;
            a = 0.f; b = 0.f;
            #pragma unroll
            for (int j = 0; j < 8 - LB8; ++j) {
                float xv = rp[j];
                wp[j] = xv;
                a += xv * sp[j];
            }
        }
        emit<LB8>(a, b, k, s_l4, s_edge, lane);

        if (tid == 0) {
            // Head leaves 0..LB8-1 belong to parent 0.
            float h = 0.f;
            #pragma unroll
            for (int j = 0; j < LB8; ++j) {
                float xv = rin[L5_START + j];
                rout[L5_START + j] = xv;
                h += xv * g_sw[L5_START + j];
            }
            s_edge[0] = h;
        }
    }
}

__global__ __launch_bounds__(512)
void tree_kernel(const float* __restrict__ in, float* __restrict__ out)
{
    __shared__ __align__(16) float s_l4[L4_COUNT];   // raw (pre-clamp) sums
    __shared__ float s_edge[132];
    __shared__ __align__(16) float s_l3[512];
    __shared__ __align__(16) float s_l2[64];
    __shared__ __align__(16) float s_l1[8];

    const int tid = threadIdx.x;
    const int r   = blockIdx.x;
    const float* __restrict__ rin  = in  + (size_t)r * NN;
    float*       __restrict__ rout = out + (size_t)r * NN;
    const int lb8 = (8 - ((r + 1) & 7)) & 7;   // leaf-base alignment mod 8

    switch (lb8) {
        case 0: stream_phase<0>(rin, rout, s_l4, s_edge, tid); break;
        case 1: stream_phase<1>(rin, rout, s_l4, s_edge, tid); break;
        case 2: stream_phase<2>(rin, rout, s_l4, s_edge, tid); break;
        case 3: stream_phase<3>(rin, rout, s_l4, s_edge, tid); break;
        case 4: stream_phase<4>(rin, rout, s_l4, s_edge, tid); break;
        case 5: stream_phase<5>(rin, rout, s_l4, s_edge, tid); break;
        case 6: stream_phase<6>(rin, rout, s_l4, s_edge, tid); break;
        default: stream_phase<7>(rin, rout, s_l4, s_edge, tid); break;
    }
    __syncthreads();
    if (lb8 != 0 && tid < 128) s_l4[tid * 32] += s_edge[tid];  // b-edges + head
    __syncthreads();

    // ---- Level 3: 512 parents from clamped L4 values ----
    {
        const float4* p = reinterpret_cast<const float4*>(s_l4) + 2 * tid;
        float4 va = p[0], vb = p[1];
        float c0 = __saturatef(va.x), c1 = __saturatef(va.y);
        float c2 = __saturatef(va.z), c3 = __saturatef(va.w);
        float c4 = __saturatef(vb.x), c5 = __saturatef(vb.y);
        float c6 = __saturatef(vb.z), c7 = __saturatef(vb.w);
        const float* swp = g_sw + L4_START + 8 * tid;
        float v = c0 * __ldg(swp + 0) + c1 * __ldg(swp + 1)
                + c2 * __ldg(swp + 2) + c3 * __ldg(swp + 3)
                + c4 * __ldg(swp + 4) + c5 * __ldg(swp + 5)
                + c6 * __ldg(swp + 6) + c7 * __ldg(swp + 7);
        s_l3[tid] = __saturatef(v);
    }
    __syncthreads();

    // ---- Level 2 ----
    if (tid < 64) {
        const float4* p = reinterpret_cast<const float4*>(s_l3) + 2 * tid;
        float4 va = p[0], vb = p[1];
        const float* swp = g_sw + L3_START + 8 * tid;
        float v = va.x * __ldg(swp + 0) + va.y * __ldg(swp + 1)
                + va.z * __ldg(swp + 2) + va.w * __ldg(swp + 3)
                + vb.x * __ldg(swp + 4) + vb.y * __ldg(swp + 5)
                + vb.z * __ldg(swp + 6) + vb.w * __ldg(swp + 7);
        s_l2[tid] = __saturatef(v);
    }
    __syncthreads();

    // ---- Level 1 ----
    if (tid < 8) {
        const float4* p = reinterpret_cast<const float4*>(s_l2) + 2 * tid;
        float4 va = p[0], vb = p[1];
        const float* swp = g_sw + L2_START + 8 * tid;
        float v = va.x * __ldg(swp + 0) + va.y * __ldg(swp + 1)
                + va.z * __ldg(swp + 2) + va.w * __ldg(swp + 3)
                + vb.x * __ldg(swp + 4) + vb.y * __ldg(swp + 5)
                + vb.z * __ldg(swp + 6) + vb.w * __ldg(swp + 7);
        s_l1[tid] = __saturatef(v);
    }
    __syncthreads();

    // ---- Root ----
    if (tid == 0) {
        const float4* p = reinterpret_cast<const float4*>(s_l1);
        float4 va = p[0], vb = p[1];
        const float* swp = g_sw + L1_START;
        float v = va.x * __ldg(swp + 0) + va.y * __ldg(swp + 1)
                + va.z * __ldg(swp + 2) + va.w * __ldg(swp + 3)
                + vb.x * __ldg(swp + 4) + vb.y * __ldg(swp + 5)
                + vb.z * __ldg(swp + 6) + vb.w * __ldg(swp + 7);
        rout[0] = __saturatef(v);
    }

    // ---- Write internal levels (coalesced) ----
    #pragma unroll
    for (int it = 0; it < 8; ++it) {
        int i = it * 512 + tid;
        rout[L4_START + i] = __saturatef(s_l4[i]);
    }
    rout[L3_START + tid] = s_l3[tid];
    if (tid < 64) rout[L2_START + tid] = s_l2[tid];
    if (tid < 8)  rout[L1_START + tid] = s_l1[tid];
}

extern "C" void kernel_launch(void* const* d_in, const int* in_sizes, int n_in,
                              void* d_out, int out_size) {
    const float* probs = (const float*)d_in[0];   // [2048, 37449] fp32
    const float* w     = (const float*)d_in[1];   // [37449] fp32
    float* out         = (float*)d_out;

    const int batch = in_sizes[0] / NN;           // 2048

    setup_kernel<<<(NN + 255) / 256, 256>>>(w);
    tree_kernel<<<batch, 512>>>(probs, out);
}

// round 15
// speedup vs baseline: 1.1990x; 1.1990x over previous
#include <cuda_runtime.h>
#include <cstdint>

#define NN        37449   // total nodes
#define L5_START  4681    // leaf level start
#define L5_COUNT  32768
#define L4_START  585
#define L4_COUNT  4096
#define L3_START  73
#define L2_START  9
#define L1_START  1

// sigmoid(w) for all nodes (internal-level dots + head/tail scalars)
__device__ float g_sw[NN];
// 8 shifted copies of the leaf section: copy s stores leaf l at index
// ((8-s)&7)+l. For LB8=s, vector k's 8 leaves start at copy index
// ((8-s)&7)+s+8k (= 8+8k for s>0, 8k for s=0) -> 32B aligned.
__device__ __align__(32) float g_swl8[8][L5_COUNT + 8];

__global__ void setup_kernel(const float* __restrict__ w) {
    int i = blockIdx.x * blockDim.x + threadIdx.x;
    if (i >= NN) return;
    float sv = 1.0f / (1.0f + __expf(-w[i]));
    g_sw[i] = sv;
    int l = i - L5_START;
    if (l >= 0) {
        #pragma unroll
        for (int s = 0; s < 8; ++s)
            g_swl8[s][((8 - s) & 7) + l] = sv;
    }
}

// ---- 256-bit global memory ops (sm_100+) ----
// Input leaf stream: replay-invariant -> keep-in-L2 hint.
__device__ __forceinline__ void ldg256_keep(float* v, const float* p) {
    asm volatile("ld.global.nc.L2::evict_last.v8.f32 {%0,%1,%2,%3,%4,%5,%6,%7}, [%8];"
                 : "=f"(v[0]), "=f"(v[1]), "=f"(v[2]), "=f"(v[3]),
                   "=f"(v[4]), "=f"(v[5]), "=f"(v[6]), "=f"(v[7])
                 : "l"(p));
}
__device__ __forceinline__ void ldg256(float* v, const float* p) {
    asm volatile("ld.global.nc.v8.f32 {%0,%1,%2,%3,%4,%5,%6,%7}, [%8];"
                 : "=f"(v[0]), "=f"(v[1]), "=f"(v[2]), "=f"(v[3]),
                   "=f"(v[4]), "=f"(v[5]), "=f"(v[6]), "=f"(v[7])
                 : "l"(p));
}
__device__ __forceinline__ void stg256(float* p, const float* v) {
    asm volatile("st.global.v8.f32 [%0], {%1,%2,%3,%4,%5,%6,%7,%8};"
                 :: "l"(p), "f"(v[0]), "f"(v[1]), "f"(v[2]), "f"(v[3]),
                    "f"(v[4]), "f"(v[5]), "f"(v[6]), "f"(v[7])
                 : "memory");
}

// Vector k covers leaves [LB8+8k, LB8+8k+8): a -> parent k (first 8-LB8
// products), b -> parent k+1 (last LB8 products). Parent k = a[k] + b[k-1].
template<int LB8>
__device__ __forceinline__ void vec_ab(const float* x, const float* sv,
                                       float& a, float& b)
{
    float p[8];
    #pragma unroll
    for (int i = 0; i < 8; ++i) p[i] = x[i] * sv[i];
    a = 0.f; b = 0.f;
    #pragma unroll
    for (int i = 0; i < 8 - LB8; ++i) a += p[i];
    #pragma unroll
    for (int i = 8 - LB8; i < 8; ++i) b += p[i];
}

template<int LB8>
__device__ __forceinline__ void emit(float a, float b, int k,
                                     float* __restrict__ s_l4,
                                     float* __restrict__ s_edge, int lane)
{
    if (LB8 == 0) {
        s_l4[k] = a;                       // vector k IS parent k
    } else {
        float bprev = __shfl_up_sync(0xffffffffu, b, 1);
        float val = a;
        if (lane > 0) val += bprev;        // lane-0 parents patched in fixup
        s_l4[k] = val;
        if (lane == 31) s_edge[(k >> 5) + 1] = b;  // feeds parent k+1
    }
}

template<int LB8>
__device__ __forceinline__ void stream_phase(
    const float* __restrict__ rin, float* __restrict__ rout,
    float* __restrict__ s_l4, float* __restrict__ s_edge, int tid)
{
    const float* __restrict__ xb  = rin  + L5_START + LB8;   // 32B aligned
    float*       __restrict__ ob  = rout + L5_START + LB8;   // 32B aligned
    const float* __restrict__ swb = &g_swl8[LB8][LB8 ? 8 : 0];
    const int lane = tid & 31;

    const int NFULL = (LB8 == 0) ? 8 : 7;   // full 512-vector iterations
    #pragma unroll 2
    for (int it = 0; it < NFULL; ++it) {
        const int k = it * 512 + tid;
        float x[8], sv[8];
        ldg256_keep(x, xb  + 8 * k);
        ldg256(sv,     swb + 8 * k);
        stg256(ob + 8 * k, x);
        float a, b;
        vec_ab<LB8>(x, sv, a, b);
        emit<LB8>(a, b, k, s_l4, s_edge, lane);
    }

    if (LB8 != 0) {
        // Peeled it==7: vector 4095 is clipped (only 8-LB8 leaves exist).
        const int k = 7 * 512 + tid;
        float a, b;
        if (k != 4095) {
            float x[8], sv[8];
            ldg256_keep(x, xb  + 8 * k);
            ldg256(sv,     swb + 8 * k);
            stg256(ob + 8 * k, x);
            vec_ab<LB8>(x, sv, a, b);
        } else {
            const float* rp = xb  + 8 * 4095;
            float*       wp = ob  + 8 * 4095;
            const float* sp = swb + 8 * 4095;
            a = 0.f; b = 0.f;
            #pragma unroll
            for (int j = 0; j < 8 - LB8; ++j) {
                float xv = rp[j];
                wp[j] = xv;
                a += xv * sp[j];
            }
        }
        emit<LB8>(a, b, k, s_l4, s_edge, lane);

        if (tid == 0) {
            // Head leaves 0..LB8-1 belong to parent 0.
            float h = 0.f;
            #pragma unroll
            for (int j = 0; j < LB8; ++j) {
                float xv = rin[L5_START + j];
                rout[L5_START + j] = xv;
                h += xv * g_sw[L5_START + j];
            }
            s_edge[0] = h;
        }
    }
}

__global__ __launch_bounds__(512)
void tree_kernel(const float* __restrict__ in, float* __restrict__ out)
{
    __shared__ __align__(16) float s_l4[L4_COUNT];   // raw (pre-clamp) sums
    __shared__ float s_edge[132];
    __shared__ __align__(16) float s_l3[512];
    __shared__ __align__(16) float s_l2[64];
    __shared__ __align__(16) float s_l1[8];

    const int tid = threadIdx.x;
    const int r   = blockIdx.x;
    const float* __restrict__ rin  = in  + (size_t)r * NN;
    float*       __restrict__ rout = out + (size_t)r * NN;
    const int lb8 = (8 - ((r + 1) & 7)) & 7;   // leaf-base alignment mod 8

    switch (lb8) {
        case 0: stream_phase<0>(rin, rout, s_l4, s_edge, tid); break;
        case 1: stream_phase<1>(rin, rout, s_l4, s_edge, tid); break;
        case 2: stream_phase<2>(rin, rout, s_l4, s_edge, tid); break;
        case 3: stream_phase<3>(rin, rout, s_l4, s_edge, tid); break;
        case 4: stream_phase<4>(rin, rout, s_l4, s_edge, tid); break;
        case 5: stream_phase<5>(rin, rout, s_l4, s_edge, tid); break;
        case 6: stream_phase<6>(rin, rout, s_l4, s_edge, tid); break;
        default: stream_phase<7>(rin, rout, s_l4, s_edge, tid); break;
    }
    __syncthreads();
    if (lb8 != 0 && tid < 128) s_l4[tid * 32] += s_edge[tid];  // b-edges + head
    __syncthreads();

    // ---- Level 3: 512 parents from clamped L4 values ----
    {
        const float4* p = reinterpret_cast<const float4*>(s_l4) + 2 * tid;
        float4 va = p[0], vb = p[1];
        float c0 = __saturatef(va.x), c1 = __saturatef(va.y);
        float c2 = __saturatef(va.z), c3 = __saturatef(va.w);
        float c4 = __saturatef(vb.x), c5 = __saturatef(vb.y);
        float c6 = __saturatef(vb.z), c7 = __saturatef(vb.w);
        const float* swp = g_sw + L4_START + 8 * tid;
        float v = c0 * __ldg(swp + 0) + c1 * __ldg(swp + 1)
                + c2 * __ldg(swp + 2) + c3 * __ldg(swp + 3)
                + c4 * __ldg(swp + 4) + c5 * __ldg(swp + 5)
                + c6 * __ldg(swp + 6) + c7 * __ldg(swp + 7);
        s_l3[tid] = __saturatef(v);
    }
    __syncthreads();

    // ---- Level 2 ----
    if (tid < 64) {
        const float4* p = reinterpret_cast<const float4*>(s_l3) + 2 * tid;
        float4 va = p[0], vb = p[1];
        const float* swp = g_sw + L3_START + 8 * tid;
        float v = va.x * __ldg(swp + 0) + va.y * __ldg(swp + 1)
                + va.z * __ldg(swp + 2) + va.w * __ldg(swp + 3)
                + vb.x * __ldg(swp + 4) + vb.y * __ldg(swp + 5)
                + vb.z * __ldg(swp + 6) + vb.w * __ldg(swp + 7);
        s_l2[tid] = __saturatef(v);
    }
    __syncthreads();

    // ---- Level 1 ----
    if (tid < 8) {
        const float4* p = reinterpret_cast<const float4*>(s_l2) + 2 * tid;
        float4 va = p[0], vb = p[1];
        const float* swp = g_sw + L2_START + 8 * tid;
        float v = va.x * __ldg(swp + 0) + va.y * __ldg(swp + 1)
                + va.z * __ldg(swp + 2) + va.w * __ldg(swp + 3)
                + vb.x * __ldg(swp + 4) + vb.y * __ldg(swp + 5)
                + vb.z * __ldg(swp + 6) + vb.w * __ldg(swp + 7);
        s_l1[tid] = __saturatef(v);
    }
    __syncthreads();

    // ---- Root ----
    if (tid == 0) {
        const float4* p = reinterpret_cast<const float4*>(s_l1);
        float4 va = p[0], vb = p[1];
        const float* swp = g_sw + L1_START;
        float v = va.x * __ldg(swp + 0) + va.y * __ldg(swp + 1)
                + va.z * __ldg(swp + 2) + va.w * __ldg(swp + 3)
                + vb.x * __ldg(swp + 4) + vb.y * __ldg(swp + 5)
                + vb.z * __ldg(swp + 6) + vb.w * __ldg(swp + 7);
        rout[0] = __saturatef(v);
    }

    // ---- Write internal levels (coalesced) ----
    #pragma unroll
    for (int it = 0; it < 8; ++it) {
        int i = it * 512 + tid;
        rout[L4_START + i] = __saturatef(s_l4[i]);
    }
    rout[L3_START + tid] = s_l3[tid];
    if (tid < 64) rout[L2_START + tid] = s_l2[tid];
    if (tid < 8)  rout[L1_START + tid] = s_l1[tid];
}

extern "C" void kernel_launch(void* const* d_in, const int* in_sizes, int n_in,
                              void* d_out, int out_size) {
    const float* probs = (const float*)d_in[0];   // [2048, 37449] fp32
    const float* w     = (const float*)d_in[1];   // [37449] fp32
    float* out         = (float*)d_out;

    const int batch = in_sizes[0] / NN;           // 2048

    setup_kernel<<<(NN + 255) / 256, 256>>>(w);
    tree_kernel<<<batch, 512>>>(probs, out);
}

// round 16
// speedup vs baseline: 1.2024x; 1.0029x over previous
#include <cuda_runtime.h>
#include <cstdint>

#define NN        37449   // total nodes
#define L5_START  4681    // leaf level start
#define L5_COUNT  32768
#define L4_START  585
#define L4_COUNT  4096
#define L3_START  73
#define L2_START  9
#define L1_START  1

// sigmoid(w) for all nodes (internal-level dots + head/tail scalars)
__device__ float g_sw[NN];
// 8 shifted copies of the leaf section: copy s stores leaf l at index
// ((8-s)&7)+l. For LB8=s, vector k's 8 leaves start at copy index
// ((8-s)&7)+s+8k (= 8+8k for s>0, 8k for s=0) -> 32B aligned.
__device__ __align__(32) float g_swl8[8][L5_COUNT + 8];

__global__ void setup_kernel(const float* __restrict__ w) {
    int i = blockIdx.x * blockDim.x + threadIdx.x;
    if (i >= NN) return;
    float sv = 1.0f / (1.0f + __expf(-w[i]));
    g_sw[i] = sv;
    int l = i - L5_START;
    if (l >= 0) {
        #pragma unroll
        for (int s = 0; s < 8; ++s)
            g_swl8[s][((8 - s) & 7) + l] = sv;
    }
}

// ---- 256-bit global memory ops (sm_100+) ----
// Input leaf stream: replay-invariant -> keep-in-L2 hint.
__device__ __forceinline__ void ldg256_keep(float* v, const float* p) {
    asm volatile("ld.global.nc.L2::evict_last.v8.f32 {%0,%1,%2,%3,%4,%5,%6,%7}, [%8];"
                 : "=f"(v[0]), "=f"(v[1]), "=f"(v[2]), "=f"(v[3]),
                   "=f"(v[4]), "=f"(v[5]), "=f"(v[6]), "=f"(v[7])
                 : "l"(p));
}
__device__ __forceinline__ void ldg256(float* v, const float* p) {
    asm volatile("ld.global.nc.v8.f32 {%0,%1,%2,%3,%4,%5,%6,%7}, [%8];"
                 : "=f"(v[0]), "=f"(v[1]), "=f"(v[2]), "=f"(v[3]),
                   "=f"(v[4]), "=f"(v[5]), "=f"(v[6]), "=f"(v[7])
                 : "l"(p));
}
// Leaf output: write-once, never re-read -> write-through (no dirty L2 lines).
__device__ __forceinline__ void stg256_wt(float* p, const float* v) {
    asm volatile("st.global.wt.v8.f32 [%0], {%1,%2,%3,%4,%5,%6,%7,%8};"
                 :: "l"(p), "f"(v[0]), "f"(v[1]), "f"(v[2]), "f"(v[3]),
                    "f"(v[4]), "f"(v[5]), "f"(v[6]), "f"(v[7])
                 : "memory");
}

// Vector k covers leaves [LB8+8k, LB8+8k+8): a -> parent k (first 8-LB8
// products), b -> parent k+1 (last LB8 products). Parent k = a[k] + b[k-1].
template<int LB8>
__device__ __forceinline__ void vec_ab(const float* x, const float* sv,
                                       float& a, float& b)
{
    float p[8];
    #pragma unroll
    for (int i = 0; i < 8; ++i) p[i] = x[i] * sv[i];
    a = 0.f; b = 0.f;
    #pragma unroll
    for (int i = 0; i < 8 - LB8; ++i) a += p[i];
    #pragma unroll
    for (int i = 8 - LB8; i < 8; ++i) b += p[i];
}

template<int LB8>
__device__ __forceinline__ void emit(float a, float b, int k,
                                     float* __restrict__ s_l4,
                                     float* __restrict__ s_edge, int lane)
{
    if (LB8 == 0) {
        s_l4[k] = a;                       // vector k IS parent k
    } else {
        float bprev = __shfl_up_sync(0xffffffffu, b, 1);
        float val = a;
        if (lane > 0) val += bprev;        // lane-0 parents patched in fixup
        s_l4[k] = val;
        if (lane == 31) s_edge[(k >> 5) + 1] = b;  // feeds parent k+1
    }
}

template<int LB8>
__device__ __forceinline__ void stream_phase(
    const float* __restrict__ rin, float* __restrict__ rout,
    float* __restrict__ s_l4, float* __restrict__ s_edge, int tid)
{
    const float* __restrict__ xb  = rin  + L5_START + LB8;   // 32B aligned
    float*       __restrict__ ob  = rout + L5_START + LB8;   // 32B aligned
    const float* __restrict__ swb = &g_swl8[LB8][LB8 ? 8 : 0];
    const int lane = tid & 31;

    const int NFULL = (LB8 == 0) ? 8 : 7;   // full 512-vector iterations
    #pragma unroll 2
    for (int it = 0; it < NFULL; ++it) {
        const int k = it * 512 + tid;
        float x[8], sv[8];
        ldg256_keep(x, xb  + 8 * k);
        ldg256(sv,     swb + 8 * k);
        stg256_wt(ob + 8 * k, x);
        float a, b;
        vec_ab<LB8>(x, sv, a, b);
        emit<LB8>(a, b, k, s_l4, s_edge, lane);
    }

    if (LB8 != 0) {
        // Peeled it==7: vector 4095 is clipped (only 8-LB8 leaves exist).
        const int k = 7 * 512 + tid;
        float a, b;
        if (k != 4095) {
            float x[8], sv[8];
            ldg256_keep(x, xb  + 8 * k);
            ldg256(sv,     swb + 8 * k);
            stg256_wt(ob + 8 * k, x);
            vec_ab<LB8>(x, sv, a, b);
        } else {
            const float* rp = xb  + 8 * 4095;
            float*       wp = ob  + 8 * 4095;
            const float* sp = swb + 8 * 4095;
            a = 0.f; b = 0.f;
            #pragma unroll
            for (int j = 0; j < 8 - LB8; ++j) {
                float xv = rp[j];
                wp[j] = xv;
                a += xv * sp[j];
            }
        }
        emit<LB8>(a, b, k, s_l4, s_edge, lane);

        if (tid == 0) {
            // Head leaves 0..LB8-1 belong to parent 0.
            float h = 0.f;
            #pragma unroll
            for (int j = 0; j < LB8; ++j) {
                float xv = rin[L5_START + j];
                rout[L5_START + j] = xv;
                h += xv * g_sw[L5_START + j];
            }
            s_edge[0] = h;
        }
    }
}

__global__ __launch_bounds__(512)
void tree_kernel(const float* __restrict__ in, float* __restrict__ out)
{
    __shared__ __align__(16) float s_l4[L4_COUNT];   // raw (pre-clamp) sums
    __shared__ float s_edge[132];
    __shared__ __align__(16) float s_l3[512];
    __shared__ __align__(16) float s_l2[64];
    __shared__ __align__(16) float s_l1[8];

    const int tid = threadIdx.x;
    const int r   = blockIdx.x;
    const float* __restrict__ rin  = in  + (size_t)r * NN;
    float*       __restrict__ rout = out + (size_t)r * NN;
    const int lb8 = (8 - ((r + 1) & 7)) & 7;   // leaf-base alignment mod 8

    switch (lb8) {
        case 0: stream_phase<0>(rin, rout, s_l4, s_edge, tid); break;
        case 1: stream_phase<1>(rin, rout, s_l4, s_edge, tid); break;
        case 2: stream_phase<2>(rin, rout, s_l4, s_edge, tid); break;
        case 3: stream_phase<3>(rin, rout, s_l4, s_edge, tid); break;
        case 4: stream_phase<4>(rin, rout, s_l4, s_edge, tid); break;
        case 5: stream_phase<5>(rin, rout, s_l4, s_edge, tid); break;
        case 6: stream_phase<6>(rin, rout, s_l4, s_edge, tid); break;
        default: stream_phase<7>(rin, rout, s_l4, s_edge, tid); break;
    }
    __syncthreads();
    if (lb8 != 0 && tid < 128) s_l4[tid * 32] += s_edge[tid];  // b-edges + head
    __syncthreads();

    // ---- Level 3: 512 parents from clamped L4 values ----
    {
        const float4* p = reinterpret_cast<const float4*>(s_l4) + 2 * tid;
        float4 va = p[0], vb = p[1];
        float c0 = __saturatef(va.x), c1 = __saturatef(va.y);
        float c2 = __saturatef(va.z), c3 = __saturatef(va.w);
        float c4 = __saturatef(vb.x), c5 = __saturatef(vb.y);
        float c6 = __saturatef(vb.z), c7 = __saturatef(vb.w);
        const float* swp = g_sw + L4_START + 8 * tid;
        float v = c0 * __ldg(swp + 0) + c1 * __ldg(swp + 1)
                + c2 * __ldg(swp + 2) + c3 * __ldg(swp + 3)
                + c4 * __ldg(swp + 4) + c5 * __ldg(swp + 5)
                + c6 * __ldg(swp + 6) + c7 * __ldg(swp + 7);
        s_l3[tid] = __saturatef(v);
    }
    __syncthreads();

    // ---- Level 2 ----
    if (tid < 64) {
        const float4* p = reinterpret_cast<const float4*>(s_l3) + 2 * tid;
        float4 va = p[0], vb = p[1];
        const float* swp = g_sw + L3_START + 8 * tid;
        float v = va.x * __ldg(swp + 0) + va.y * __ldg(swp + 1)
                + va.z * __ldg(swp + 2) + va.w * __ldg(swp + 3)
                + vb.x * __ldg(swp + 4) + vb.y * __ldg(swp + 5)
                + vb.z * __ldg(swp + 6) + vb.w * __ldg(swp + 7);
        s_l2[tid] = __saturatef(v);
    }
    __syncthreads();

    // ---- Level 1 ----
    if (tid < 8) {
        const float4* p = reinterpret_cast<const float4*>(s_l2) + 2 * tid;
        float4 va = p[0], vb = p[1];
        const float* swp = g_sw + L2_START + 8 * tid;
        float v = va.x * __ldg(swp + 0) + va.y * __ldg(swp + 1)
                + va.z * __ldg(swp + 2) + va.w * __ldg(swp + 3)
                + vb.x * __ldg(swp + 4) + vb.y * __ldg(swp + 5)
                + vb.z * __ldg(swp + 6) + vb.w * __ldg(swp + 7);
        s_l1[tid] = __saturatef(v);
    }
    __syncthreads();

    // ---- Root ----
    if (tid == 0) {
        const float4* p = reinterpret_cast<const float4*>(s_l1);
        float4 va = p[0], vb = p[1];
        const float* swp = g_sw + L1_START;
        float v = va.x * __ldg(swp + 0) + va.y * __ldg(swp + 1)
                + va.z * __ldg(swp + 2) + va.w * __ldg(swp + 3)
                + vb.x * __ldg(swp + 4) + vb.y * __ldg(swp + 5)
                + vb.z * __ldg(swp + 6) + vb.w * __ldg(swp + 7);
        rout[0] = __saturatef(v);
    }

    // ---- Write internal levels (coalesced, default policy) ----
    #pragma unroll
    for (int it = 0; it < 8; ++it) {
        int i = it * 512 + tid;
        rout[L4_START + i] = __saturatef(s_l4[i]);
    }
    rout[L3_START + tid] = s_l3[tid];
    if (tid < 64) rout[L2_START + tid] = s_l2[tid];
    if (tid < 8)  rout[L1_START + tid] = s_l1[tid];
}

extern "C" void kernel_launch(void* const* d_in, const int* in_sizes, int n_in,
                              void* d_out, int out_size) {
    const float* probs = (const float*)d_in[0];   // [2048, 37449] fp32
    const float* w     = (const float*)d_in[1];   // [37449] fp32
    float* out         = (float*)d_out;

    const int batch = in_sizes[0] / NN;           // 2048

    setup_kernel<<<(NN + 255) / 256, 256>>>(w);
    tree_kernel<<<batch, 512>>>(probs, out);
}

// round 17
// speedup vs baseline: 1.2269x; 1.0204x over previous
#include <cuda_runtime.h>
#include <cstdint>

#define NN        37449   // total nodes
#define L5_START  4681    // leaf level start
#define L5_COUNT  32768
#define L4_START  585
#define L4_COUNT  4096
#define L3_START  73
#define L2_START  9
#define L1_START  1

// sigmoid(w) for all nodes (internal-level dots + head/tail scalars)
__device__ float g_sw[NN];
// 8 shifted copies of the leaf section: copy s stores leaf l at index
// ((8-s)&7)+l. For LB8=s, vector k's 8 leaves start at copy index
// ((8-s)&7)+s+8k (= 8+8k for s>0, 8k for s=0) -> 32B aligned.
__device__ __align__(32) float g_swl8[8][L5_COUNT + 8];

__global__ void setup_kernel(const float* __restrict__ w) {
    int i = blockIdx.x * blockDim.x + threadIdx.x;
    if (i < NN) {
        float sv = 1.0f / (1.0f + __expf(-w[i]));
        g_sw[i] = sv;
        int l = i - L5_START;
        if (l >= 0) {
            #pragma unroll
            for (int s = 0; s < 8; ++s)
                g_swl8[s][((8 - s) & 7) + l] = sv;
        }
    }
#if __CUDA_ARCH__ >= 900
    cudaTriggerProgrammaticLaunchCompletion();
#endif
}

// ---- 256-bit global memory ops (sm_100+) ----
// Input leaf stream: replay-invariant -> keep-in-L2 hint.
__device__ __forceinline__ void ldg256_keep(float* v, const float* p) {
    asm volatile("ld.global.nc.L2::evict_last.v8.f32 {%0,%1,%2,%3,%4,%5,%6,%7}, [%8];"
                 : "=f"(v[0]), "=f"(v[1]), "=f"(v[2]), "=f"(v[3]),
                   "=f"(v[4]), "=f"(v[5]), "=f"(v[6]), "=f"(v[7])
                 : "l"(p));
}
__device__ __forceinline__ void ldg256(float* v, const float* p) {
    asm volatile("ld.global.nc.v8.f32 {%0,%1,%2,%3,%4,%5,%6,%7}, [%8];"
                 : "=f"(v[0]), "=f"(v[1]), "=f"(v[2]), "=f"(v[3]),
                   "=f"(v[4]), "=f"(v[5]), "=f"(v[6]), "=f"(v[7])
                 : "l"(p));
}
// Leaf output: write-once, never re-read -> write-through (no dirty L2 lines).
__device__ __forceinline__ void stg256_wt(float* p, const float* v) {
    asm volatile("st.global.wt.v8.f32 [%0], {%1,%2,%3,%4,%5,%6,%7,%8};"
                 :: "l"(p), "f"(v[0]), "f"(v[1]), "f"(v[2]), "f"(v[3]),
                    "f"(v[4]), "f"(v[5]), "f"(v[6]), "f"(v[7])
                 : "memory");
}

// Vector k covers leaves [LB8+8k, LB8+8k+8): a -> parent k (first 8-LB8
// products), b -> parent k+1 (last LB8 products). Parent k = a[k] + b[k-1].
template<int LB8>
__device__ __forceinline__ void vec_ab(const float* x, const float* sv,
                                       float& a, float& b)
{
    float p[8];
    #pragma unroll
    for (int i = 0; i < 8; ++i) p[i] = x[i] * sv[i];
    a = 0.f; b = 0.f;
    #pragma unroll
    for (int i = 0; i < 8 - LB8; ++i) a += p[i];
    #pragma unroll
    for (int i = 8 - LB8; i < 8; ++i) b += p[i];
}

template<int LB8>
__device__ __forceinline__ void emit(float a, float b, int k,
                                     float* __restrict__ s_l4,
                                     float* __restrict__ s_edge, int lane)
{
    if (LB8 == 0) {
        s_l4[k] = a;                       // vector k IS parent k
    } else {
        float bprev = __shfl_up_sync(0xffffffffu, b, 1);
        float val = a;
        if (lane > 0) val += bprev;        // lane-0 parents patched in fixup
        s_l4[k] = val;
        if (lane == 31) s_edge[(k >> 5) + 1] = b;  // feeds parent k+1
    }
}

template<int LB8>
__device__ __forceinline__ void stream_phase(
    const float* __restrict__ rin, float* __restrict__ rout,
    float* __restrict__ s_l4, float* __restrict__ s_edge, int tid)
{
    const float* __restrict__ xb  = rin  + L5_START + LB8;   // 32B aligned
    float*       __restrict__ ob  = rout + L5_START + LB8;   // 32B aligned
    const float* __restrict__ swb = &g_swl8[LB8][LB8 ? 8 : 0];
    const int lane = tid & 31;

    // ---- Iteration 0 peeled: x load + store do NOT depend on setup_kernel.
    // Issue them, then wait for setup's sw tables (PDL overlap window).
    {
        const int k = tid;
        float x[8], sv[8];
        ldg256_keep(x, xb + 8 * k);
        stg256_wt(ob + 8 * k, x);
#if __CUDA_ARCH__ >= 900
        cudaGridDependencySynchronize();   // setup's g_sw/g_swl8 now visible
#endif
        ldg256(sv, swb + 8 * k);
        float a, b;
        vec_ab<LB8>(x, sv, a, b);
        emit<LB8>(a, b, k, s_l4, s_edge, lane);
    }

    const int NFULL = (LB8 == 0) ? 8 : 7;   // full 512-vector iterations
    #pragma unroll 2
    for (int it = 1; it < NFULL; ++it) {
        const int k = it * 512 + tid;
        float x[8], sv[8];
        ldg256_keep(x, xb  + 8 * k);
        ldg256(sv,     swb + 8 * k);
        stg256_wt(ob + 8 * k, x);
        float a, b;
        vec_ab<LB8>(x, sv, a, b);
        emit<LB8>(a, b, k, s_l4, s_edge, lane);
    }

    if (LB8 != 0) {
        // Peeled it==7: vector 4095 is clipped (only 8-LB8 leaves exist).
        const int k = 7 * 512 + tid;
        float a, b;
        if (k != 4095) {
            float x[8], sv[8];
            ldg256_keep(x, xb  + 8 * k);
            ldg256(sv,     swb + 8 * k);
            stg256_wt(ob + 8 * k, x);
            vec_ab<LB8>(x, sv, a, b);
        } else {
            const float* rp = xb  + 8 * 4095;
            float*       wp = ob  + 8 * 4095;
            const float* sp = swb + 8 * 4095;
            a = 0.f; b = 0.f;
            #pragma unroll
            for (int j = 0; j < 8 - LB8; ++j) {
                float xv = rp[j];
                wp[j] = xv;
                a += xv * sp[j];
            }
        }
        emit<LB8>(a, b, k, s_l4, s_edge, lane);

        if (tid == 0) {
            // Head leaves 0..LB8-1 belong to parent 0.
            float h = 0.f;
            #pragma unroll
            for (int j = 0; j < LB8; ++j) {
                float xv = rin[L5_START + j];
                rout[L5_START + j] = xv;
                h += xv * g_sw[L5_START + j];
            }
            s_edge[0] = h;
        }
    }
}

__global__ __launch_bounds__(512)
void tree_kernel(const float* __restrict__ in, float* __restrict__ out)
{
    __shared__ __align__(16) float s_l4[L4_COUNT];   // raw (pre-clamp) sums
    __shared__ float s_edge[132];
    __shared__ __align__(16) float s_l3[512];
    __shared__ __align__(16) float s_l2[64];
    __shared__ __align__(16) float s_l1[8];

    const int tid = threadIdx.x;
    const int r   = blockIdx.x;
    const float* __restrict__ rin  = in  + (size_t)r * NN;
    float*       __restrict__ rout = out + (size_t)r * NN;
    const int lb8 = (8 - ((r + 1) & 7)) & 7;   // leaf-base alignment mod 8

    switch (lb8) {
        case 0: stream_phase<0>(rin, rout, s_l4, s_edge, tid); break;
        case 1: stream_phase<1>(rin, rout, s_l4, s_edge, tid); break;
        case 2: stream_phase<2>(rin, rout, s_l4, s_edge, tid); break;
        case 3: stream_phase<3>(rin, rout, s_l4, s_edge, tid); break;
        case 4: stream_phase<4>(rin, rout, s_l4, s_edge, tid); break;
        case 5: stream_phase<5>(rin, rout, s_l4, s_edge, tid); break;
        case 6: stream_phase<6>(rin, rout, s_l4, s_edge, tid); break;
        default: stream_phase<7>(rin, rout, s_l4, s_edge, tid); break;
    }
    __syncthreads();
    if (lb8 != 0 && tid < 128) s_l4[tid * 32] += s_edge[tid];  // b-edges + head
    __syncthreads();

    // ---- Level 3: 512 parents from clamped L4 values ----
    {
        const float4* p = reinterpret_cast<const float4*>(s_l4) + 2 * tid;
        float4 va = p[0], vb = p[1];
        float c0 = __saturatef(va.x), c1 = __saturatef(va.y);
        float c2 = __saturatef(va.z), c3 = __saturatef(va.w);
        float c4 = __saturatef(vb.x), c5 = __saturatef(vb.y);
        float c6 = __saturatef(vb.z), c7 = __saturatef(vb.w);
        const float* swp = g_sw + L4_START + 8 * tid;
        float v = c0 * __ldg(swp + 0) + c1 * __ldg(swp + 1)
                + c2 * __ldg(swp + 2) + c3 * __ldg(swp + 3)
                + c4 * __ldg(swp + 4) + c5 * __ldg(swp + 5)
                + c6 * __ldg(swp + 6) + c7 * __ldg(swp + 7);
        s_l3[tid] = __saturatef(v);
    }
    __syncthreads();

    // ---- Level 2 ----
    if (tid < 64) {
        const float4* p = reinterpret_cast<const float4*>(s_l3) + 2 * tid;
        float4 va = p[0], vb = p[1];
        const float* swp = g_sw + L3_START + 8 * tid;
        float v = va.x * __ldg(swp + 0) + va.y * __ldg(swp + 1)
                + va.z * __ldg(swp + 2) + va.w * __ldg(swp + 3)
                + vb.x * __ldg(swp + 4) + vb.y * __ldg(swp + 5)
                + vb.z * __ldg(swp + 6) + vb.w * __ldg(swp + 7);
        s_l2[tid] = __saturatef(v);
    }
    __syncthreads();

    // ---- Level 1 ----
    if (tid < 8) {
        const float4* p = reinterpret_cast<const float4*>(s_l2) + 2 * tid;
        float4 va = p[0], vb = p[1];
        const float* swp = g_sw + L2_START + 8 * tid;
        float v = va.x * __ldg(swp + 0) + va.y * __ldg(swp + 1)
                + va.z * __ldg(swp + 2) + va.w * __ldg(swp + 3)
                + vb.x * __ldg(swp + 4) + vb.y * __ldg(swp + 5)
                + vb.z * __ldg(swp + 6) + vb.w * __ldg(swp + 7);
        s_l1[tid] = __saturatef(v);
    }
    __syncthreads();

    // ---- Root ----
    if (tid == 0) {
        const float4* p = reinterpret_cast<const float4*>(s_l1);
        float4 va = p[0], vb = p[1];
        const float* swp = g_sw + L1_START;
        float v = va.x * __ldg(swp + 0) + va.y * __ldg(swp + 1)
                + va.z * __ldg(swp + 2) + va.w * __ldg(swp + 3)
                + vb.x * __ldg(swp + 4) + vb.y * __ldg(swp + 5)
                + vb.z * __ldg(swp + 6) + vb.w * __ldg(swp + 7);
        rout[0] = __saturatef(v);
    }

    // ---- Write internal levels (coalesced, default policy) ----
    #pragma unroll
    for (int it = 0; it < 8; ++it) {
        int i = it * 512 + tid;
        rout[L4_START + i] = __saturatef(s_l4[i]);
    }
    rout[L3_START + tid] = s_l3[tid];
    if (tid < 64) rout[L2_START + tid] = s_l2[tid];
    if (tid < 8)  rout[L1_START + tid] = s_l1[tid];
}

extern "C" void kernel_launch(void* const* d_in, const int* in_sizes, int n_in,
                              void* d_out, int out_size) {
    const float* probs = (const float*)d_in[0];   // [2048, 37449] fp32
    const float* w     = (const float*)d_in[1];   // [37449] fp32
    float* out         = (float*)d_out;

    const int batch = in_sizes[0] / NN;           // 2048

    setup_kernel<<<(NN + 255) / 256, 256>>>(w);

    // PDL: tree_kernel launches while setup drains; blocks sync on its
    // completion only right before consuming the sw tables.
    cudaLaunchConfig_t cfg = {};
    cfg.gridDim  = dim3((unsigned)batch, 1, 1);
    cfg.blockDim = dim3(512, 1, 1);
    cudaLaunchAttribute attrs[1];
    attrs[0].id = cudaLaunchAttributeProgrammaticStreamSerialization;
    attrs[0].val.programmaticStreamSerializationAllowed = 1;
    cfg.attrs = attrs;
    cfg.numAttrs = 1;
    cudaLaunchKernelEx(&cfg, tree_kernel, probs, out);
}